// round 15
// baseline (speedup 1.0000x reference)
#include <cuda_runtime.h>
#include <cuda_fp16.h>
#include <stdint.h>
#include <math.h>

// ---------------- problem constants ----------------
#define BN_ 8192   // batch
#define DN_ 2048   // feature dim
#define NI_ 1023   // inner nodes
#define NL_ 1024   // leaves / padded inner count
#define CN_ 1000   // classes

// ---------------- device-global scratch ----------------
__device__ __half g_xh[(size_t)BN_ * DN_];        // x in fp16
__device__ __half g_WhT[NL_ * DN_];               // W^T padded fp16: [1024 n][2048 k]
__device__ float  g_bp[NL_];
__device__ float  g_dec[(size_t)BN_ * NL_];       // decisions [8192][1024] (fp32)
__device__ __half g_pph[(size_t)BN_ * NL_];       // path probs fp16 [8192][1024]
__device__ float  g_lp[NL_ * NL_];                // softmax(leaf) fp32 [1024][1024]
__device__ __half g_lpTh[NL_ * NL_];              // transposed fp16 [1024 cls][1024 leaf]

// ---------------- pipeline state (re-zeroed every launch by prep kernel) ----------------
__device__ int g_ticket;
__device__ int g_cxdone[64];    // convert_x done per 128-row block (target 1)
__device__ int g_smdone;        // softmax tickets done (target 32)
__device__ int g_g1cnt[64];     // GEMM1 tiles done per 128-row block (target 8)
__device__ int g_ppdone[64];    // pp tickets done per 128-row block (target 4)
__device__ int g_lpdone;        // lp-transpose tickets done (target 128)

// ---------------- helpers ----------------
__device__ __forceinline__ uint32_t smem_u32(const void* p) {
    uint32_t a;
    asm("{ .reg .u64 t; cvta.to.shared.u64 t, %1; cvt.u32.u64 %0, t; }" : "=r"(a) : "l"(p));
    return a;
}
__device__ __forceinline__ void cpasync16(uint32_t dst, const void* src) {
    asm volatile("cp.async.cg.shared.global [%0], [%1], 16;" :: "r"(dst), "l"(src) : "memory");
}
__device__ __forceinline__ void ldsm4(uint32_t* r, uint32_t addr) {
    asm volatile("ldmatrix.sync.aligned.m8n8.x4.shared.b16 {%0,%1,%2,%3}, [%4];"
        : "=r"(r[0]), "=r"(r[1]), "=r"(r[2]), "=r"(r[3]) : "r"(addr));
}
__device__ __forceinline__ void mma16816(float* d, const uint32_t* a, uint32_t b0, uint32_t b1) {
    asm volatile("mma.sync.aligned.m16n8k16.row.col.f32.f16.f16.f32 "
        "{%0,%1,%2,%3}, {%4,%5,%6,%7}, {%8,%9}, {%0,%1,%2,%3};"
        : "+f"(d[0]), "+f"(d[1]), "+f"(d[2]), "+f"(d[3])
        : "r"(a[0]), "r"(a[1]), "r"(a[2]), "r"(a[3]), "r"(b0), "r"(b1));
}

// ================= small prep: transpose_W | pad_b | zero-state =================
// blocks: [0,2048) transpose_W, [2048,2052) pad_b, [2052] zero-state
#define PREP_PB   2048
#define PREP_ZB   2052
#define PREP_GRID 2053

__global__ __launch_bounds__(256) void prep_kernel(
    const float* __restrict__ W, const float* __restrict__ b)
{
    __shared__ float t[32 * 33];
    int bid = blockIdx.x;
    int tid = threadIdx.x;

    if (bid < PREP_PB) {
        // ---- W [2048 k][1023 n] -> g_WhT [1024 n][2048 k] fp16, pad with 0 ----
        int k0 = (bid & 63) * 32;
        int n0 = (bid >> 6) * 32;
        int tx = tid & 31, ty = tid >> 5;
        #pragma unroll
        for (int i = 0; i < 32; i += 8) {
            int n = n0 + tx;
            t[(ty + i) * 33 + tx] = (n < NI_) ? W[(size_t)(k0 + ty + i) * NI_ + n] : 0.0f;
        }
        __syncthreads();
        #pragma unroll
        for (int i = 0; i < 32; i += 8)
            g_WhT[(size_t)(n0 + ty + i) * DN_ + k0 + tx] = __float2half_rn(t[tx * 33 + ty + i]);
    } else if (bid < PREP_ZB) {
        int i = (bid - PREP_PB) * 256 + tid;
        if (i < NL_) g_bp[i] = (i < NI_) ? b[i] : 0.0f;
    } else {
        if (tid < 64) { g_cxdone[tid] = 0; g_g1cnt[tid] = 0; g_ppdone[tid] = 0; }
        if (tid == 64) { g_smdone = 0; g_lpdone = 0; g_ticket = 0; }
    }
}

// ---------------- fp16 mma.sync GEMM tile: 128x128x64, 256 threads, 3-stage (R10/R12-verified) ----------------
#define BM   128
#define BNT  128
#define BKH  64                                   // k-tile in halves
#define STG  3
#define PADH 72                                   // halves per smem row (144B)
#define SSTAGE_H ((BM + BNT) * PADH)              // halves per stage = 18432
#define SMEM_GEMM (STG * SSTAGE_H * 2)            // 110592 bytes

template <bool SIG>
__device__ void gemm_tile(
    const __half* __restrict__ A, const __half* __restrict__ Bm,
    const float* __restrict__ bias, float* __restrict__ C,
    int K, int lda, int ldb, int ldc, int nvalid,
    int rowBase, int colBase, __half* smh)
{
    const int tid  = threadIdx.x;
    const int wid  = tid >> 5, lane = tid & 31;
    const int gid  = lane >> 2, tig = lane & 3;
    const int m0   = (wid & 3) * 32, n0 = (wid >> 2) * 64;   // warp tile 32x64
    const uint32_t sb = smem_u32(smh);

    const __half* Ag = A + (size_t)rowBase * lda;
    const __half* Bg = Bm + (size_t)colBase * ldb;

    const int lrow  = (lane & 7) + ((lane >> 3) & 1) * 8;
    const int khalf = (lane >> 4) * 8;
    uint32_t offA[2], offB[4];
    #pragma unroll
    for (int mf = 0; mf < 2; mf++)
        offA[mf] = (uint32_t)(((m0 + mf * 16 + lrow) * PADH + khalf) * 2);
    #pragma unroll
    for (int p = 0; p < 4; p++)
        offB[p] = (uint32_t)((BM * PADH + (n0 + p * 16 + lrow) * PADH + khalf) * 2);

    float acc[2][8][4];
    #pragma unroll
    for (int mf = 0; mf < 2; mf++)
        #pragma unroll
        for (int nf = 0; nf < 8; nf++)
            #pragma unroll
            for (int q = 0; q < 4; q++) acc[mf][nf][q] = 0.0f;

    const int nkt = K / BKH;

    auto load_stage = [&](int s, int kt) {
        uint32_t abase = sb + (uint32_t)(s * SSTAGE_H) * 2;
        uint32_t bbase = abase + BM * PADH * 2;
        const __half* Ak = Ag + kt * BKH;
        const __half* Bk = Bg + kt * BKH;
        #pragma unroll
        for (int i = 0; i < 4; i++) {
            int idx = tid + i * 256;
            int row = idx >> 3, ch = idx & 7;
            cpasync16(abase + (uint32_t)(row * PADH * 2 + ch * 16), Ak + (size_t)row * lda + ch * 8);
        }
        #pragma unroll
        for (int i = 0; i < 4; i++) {
            int idx = tid + i * 256;
            int row = idx >> 3, ch = idx & 7;
            cpasync16(bbase + (uint32_t)(row * PADH * 2 + ch * 16), Bk + (size_t)row * ldb + ch * 8);
        }
    };

    load_stage(0, 0);
    asm volatile("cp.async.commit_group;" ::: "memory");
    load_stage(1, 1);
    asm volatile("cp.async.commit_group;" ::: "memory");

    int stage = 0;
    for (int kt = 0; kt < nkt; kt++) {
        asm volatile("cp.async.wait_group 1;" ::: "memory");
        __syncthreads();

        if (kt + 2 < nkt) {
            int s2 = stage + 2; if (s2 >= STG) s2 -= STG;
            load_stage(s2, kt + 2);
        }
        asm volatile("cp.async.commit_group;" ::: "memory");

        uint32_t sbase = sb + (uint32_t)(stage * SSTAGE_H) * 2;
        #pragma unroll
        for (int ks = 0; ks < 4; ks++) {
            const uint32_t kb = ks * 32;
            uint32_t a[2][4], b[4][4];
            #pragma unroll
            for (int mf = 0; mf < 2; mf++) ldsm4(a[mf], sbase + offA[mf] + kb);
            #pragma unroll
            for (int p = 0; p < 4; p++)   ldsm4(b[p],  sbase + offB[p] + kb);
            #pragma unroll
            for (int mf = 0; mf < 2; mf++)
                #pragma unroll
                for (int p = 0; p < 4; p++) {
                    mma16816(acc[mf][2 * p],     a[mf], b[p][0], b[p][2]);
                    mma16816(acc[mf][2 * p + 1], a[mf], b[p][1], b[p][3]);
                }
        }
        stage++; if (stage == STG) stage = 0;
    }

    // epilogue
    #pragma unroll
    for (int mf = 0; mf < 2; mf++) {
        int r0 = rowBase + m0 + mf * 16 + gid;
        #pragma unroll
        for (int nf = 0; nf < 8; nf++) {
            int col = colBase + n0 + nf * 8 + tig * 2;
            float2 v0 = make_float2(acc[mf][nf][0], acc[mf][nf][1]);
            float2 v1 = make_float2(acc[mf][nf][2], acc[mf][nf][3]);
            if (SIG) {
                float b0 = bias[col], b1 = bias[col + 1];
                v0.x = 1.0f / (1.0f + __expf(-(v0.x + b0)));
                v0.y = 1.0f / (1.0f + __expf(-(v0.y + b1)));
                v1.x = 1.0f / (1.0f + __expf(-(v1.x + b0)));
                v1.y = 1.0f / (1.0f + __expf(-(v1.y + b1)));
            }
            if (col < nvalid) {
                *(float2*)(C + (size_t)r0 * ldc + col) = v0;
                *(float2*)(C + (size_t)(r0 + 8) * ldc + col) = v1;
            }
        }
    }
}

// ================= persistent mega-kernel: full pipeline as tickets =================
// tickets: [0,64)       convert_x (128-row block r)       -> cxdone[r]
//          [64,96)      softmax (32 leaf rows each)       -> smdone
//          [96,608)     GEMM1 tiles (r=u/8, c=u%8), wait cxdone[r]
//          [608,736)    lp transpose (8 x 32x32 tiles), wait smdone==32 -> lpdone
//          [736,992)    pp (32 rows each), wait g1cnt[r]==8 -> ppdone[r]
//          [992,1504)   GEMM2 tiles, wait lpdone==128 && ppdone[r]==4
#define T_SM   64
#define T_G1   96
#define T_LPT  608
#define T_PP   736
#define T_G2   992
#define T_TOT  1504
#define NPERS  296     // 148 SMs x 2 CTAs

__global__ __launch_bounds__(256, 2) void mega_kernel(
    float* __restrict__ out, const float* __restrict__ x, const float* __restrict__ ld)
{
    extern __shared__ __half smh[];
    float* smf = (float*)smh;
    const int tid = threadIdx.x;
    __shared__ int s_ticket;

    for (;;) {
        if (tid == 0) s_ticket = atomicAdd(&g_ticket, 1);
        __syncthreads();
        int q = s_ticket;
        if (q >= T_TOT) return;

        if (q < T_SM) {
            // ---- convert_x: 128 rows of x fp32 -> fp16 ----
            int r = q;
            size_t base = (size_t)r * 128 * DN_;
            #pragma unroll 4
            for (int it = 0; it < 64; it++) {
                size_t i = base + ((size_t)it * 256 + tid) * 16;
                #pragma unroll
                for (int qq = 0; qq < 2; qq++) {
                    float4 v0 = *(const float4*)(x + i + qq * 8);
                    float4 v1 = *(const float4*)(x + i + qq * 8 + 4);
                    __half2 h[4];
                    h[0] = __floats2half2_rn(v0.x, v0.y);
                    h[1] = __floats2half2_rn(v0.z, v0.w);
                    h[2] = __floats2half2_rn(v1.x, v1.y);
                    h[3] = __floats2half2_rn(v1.z, v1.w);
                    *(uint4*)(g_xh + i + qq * 8) = *(uint4*)h;
                }
            }
            if (tid == 0) { __threadfence(); atomicExch(&g_cxdone[r], 1); }
        } else if (q < T_G1) {
            // ---- softmax: 32 leaf rows ----
            int v = q - T_SM;
            float* sred = smf;
            for (int rr = 0; rr < 32; rr++) {
                int row = v * 32 + rr;
                const float* r = ld + (size_t)row * CN_;
                float*       o = g_lp + (size_t)row * NL_;

                float mx = -3.4e38f;
                for (int i = tid; i < CN_; i += 256) mx = fmaxf(mx, r[i]);
                #pragma unroll
                for (int s = 16; s; s >>= 1) mx = fmaxf(mx, __shfl_xor_sync(0xffffffffu, mx, s));
                if ((tid & 31) == 0) sred[tid >> 5] = mx;
                __syncthreads();
                mx = sred[0];
                #pragma unroll
                for (int w = 1; w < 8; w++) mx = fmaxf(mx, sred[w]);
                __syncthreads();

                float sum = 0.0f;
                for (int i = tid; i < CN_; i += 256) sum += __expf(r[i] - mx);
                #pragma unroll
                for (int s = 16; s; s >>= 1) sum += __shfl_xor_sync(0xffffffffu, sum, s);
                if ((tid & 31) == 0) sred[tid >> 5] = sum;
                __syncthreads();
                sum = 0.0f;
                #pragma unroll
                for (int w = 0; w < 8; w++) sum += sred[w];
                float inv = 1.0f / sum;

                for (int i = tid; i < CN_; i += 256) o[i] = __expf(r[i] - mx) * inv;
                for (int i = CN_ + tid; i < NL_; i += 256) o[i] = 0.0f;
                __syncthreads();
            }
            if (tid == 0) { __threadfence(); atomicAdd(&g_smdone, 1); }
        } else if (q < T_LPT) {
            // ---- GEMM1 tile, gated on convert_x of its row block ----
            int u = q - T_G1;
            int r = u >> 3, c = u & 7;
            if (tid == 0) {
                while (*(volatile int*)&g_cxdone[r] == 0) __nanosleep(64);
                __threadfence();
            }
            __syncthreads();
            gemm_tile<true>(g_xh, g_WhT, g_bp, g_dec,
                            DN_, DN_, DN_, NL_, NL_, r * BM, c * BNT, smh);
            __syncthreads();
            if (tid == 0) { __threadfence(); atomicAdd(&g_g1cnt[r], 1); }
        } else if (q < T_PP) {
            // ---- lp transpose: 8 tiles of 32x32, gated on softmax completion ----
            int v = q - T_LPT;
            if (tid == 0) {
                while (*(volatile int*)&g_smdone < 32) __nanosleep(64);
                __threadfence();
            }
            __syncthreads();
            int tx = tid & 31, ty = tid >> 5;
            #pragma unroll
            for (int it = 0; it < 8; it++) {
                int tile = v * 8 + it;
                int r0 = (tile & 31) * 32, c0 = (tile >> 5) * 32;
                #pragma unroll
                for (int i = 0; i < 32; i += 8)
                    smf[(ty + i) * 33 + tx] = g_lp[(size_t)(r0 + ty + i) * NL_ + c0 + tx];
                __syncthreads();
                #pragma unroll
                for (int i = 0; i < 32; i += 8)
                    g_lpTh[(size_t)(c0 + ty + i) * NL_ + r0 + tx] = __float2half_rn(smf[tx * 33 + ty + i]);
                __syncthreads();
            }
            if (tid == 0) { __threadfence(); atomicAdd(&g_lpdone, 1); }
        } else if (q < T_G2) {
            // ---- pp unwind: 32 rows, gated on GEMM1 row-block ----
            int v = q - T_PP;
            int r = v >> 2;
            if (tid == 0) {
                while (*(volatile int*)&g_g1cnt[r] < 8) __nanosleep(64);
                __threadfence();
            }
            __syncthreads();
            float* ds = smf;
            for (int rr = 0; rr < 32; rr++) {
                int row = v * 32 + rr;
                const float* dr = g_dec + (size_t)row * NL_;
                for (int i = tid; i < NL_; i += 256) ds[i] = dr[i];
                __syncthreads();
                __half* po = g_pph + (size_t)row * NL_;
                #pragma unroll
                for (int jj = 0; jj < 4; jj++) {
                    int j = tid + jj * 256;
                    float p = 1.0f;
                    int idx = j;
                    #pragma unroll
                    for (int d = 9; d >= 0; d--) {
                        int L = 1 << d;
                        int i2 = (idx < L) ? (idx << 1) : (((idx - L) << 1) | 1);
                        bool left = i2 < L;
                        int node = (L - 1) + (left ? i2 : (i2 - L));
                        float dd = ds[node];
                        p *= left ? dd : (1.0f - dd);
                        idx = i2 & (L - 1);
                    }
                    po[j] = __float2half_rn(p);
                }
                __syncthreads();
            }
            if (tid == 0) { __threadfence(); atomicAdd(&g_ppdone[r], 1); }
        } else {
            // ---- GEMM2 tile ----
            int u = q - T_G2;
            int r = u >> 3, c = u & 7;
            if (tid == 0) {
                while (*(volatile int*)&g_lpdone < 128) __nanosleep(64);
                while (*(volatile int*)&g_ppdone[r] < 4) __nanosleep(64);
                __threadfence();
            }
            __syncthreads();
            gemm_tile<false>(g_pph, g_lpTh, nullptr, out,
                             NL_, NL_, NL_, CN_, CN_, r * BM, c * BNT, smh);
            __syncthreads();
        }
    }
}

// ---------------- host launch ----------------
extern "C" void kernel_launch(void* const* d_in, const int* in_sizes, int n_in,
                              void* d_out, int out_size)
{
    const float* x    = (const float*)d_in[0];   // [8192, 2048]
    const float* W    = (const float*)d_in[1];   // [2048, 1023]
    const float* b    = (const float*)d_in[2];   // [1023]
    const float* leaf = (const float*)d_in[3];   // [1024, 1000]
    float*       out  = (float*)d_out;           // [8192, 1000]

    static bool attr_set = false;
    if (!attr_set) {
        cudaFuncSetAttribute(mega_kernel, cudaFuncAttributeMaxDynamicSharedMemorySize, SMEM_GEMM);
        attr_set = true;
    }

    // 1) small prep: transpose_W | pad_b | zero pipeline state
    prep_kernel<<<PREP_GRID, 256>>>(W, b);

    // 2) persistent pipeline: convert_x | softmax | GEMM1 | lpT | pp | GEMM2
    mega_kernel<<<NPERS, 256, SMEM_GEMM>>>(out, x, leaf);
}

// round 16
// speedup vs baseline: 1.1438x; 1.1438x over previous
#include <cuda_runtime.h>
#include <cuda_fp16.h>
#include <stdint.h>
#include <math.h>

// ---------------- problem constants ----------------
#define BN_ 8192   // batch
#define DN_ 2048   // feature dim
#define NI_ 1023   // inner nodes
#define NL_ 1024   // leaves / padded inner count
#define CN_ 1000   // classes

// ---------------- device-global scratch ----------------
__device__ __half g_xh[(size_t)BN_ * DN_];        // x in fp16
__device__ __half g_WhT[NL_ * DN_];               // W^T padded fp16: [1024 n][2048 k]
__device__ float  g_bp[NL_];
__device__ float  g_dec[(size_t)BN_ * NL_];       // decisions [8192][1024] (fp32)
__device__ __half g_pph[(size_t)BN_ * NL_];       // path probs fp16 [8192][1024]
__device__ __half g_lpTh[NL_ * NL_];              // softmax(leaf)^T fp16 [1024 cls][1024 leaf]

// ---------------- helpers ----------------
__device__ __forceinline__ uint32_t smem_u32(const void* p) {
    uint32_t a;
    asm("{ .reg .u64 t; cvta.to.shared.u64 t, %1; cvt.u32.u64 %0, t; }" : "=r"(a) : "l"(p));
    return a;
}
__device__ __forceinline__ void cpasync16(uint32_t dst, const void* src) {
    asm volatile("cp.async.cg.shared.global [%0], [%1], 16;" :: "r"(dst), "l"(src) : "memory");
}
__device__ __forceinline__ void ldsm4(uint32_t* r, uint32_t addr) {
    asm volatile("ldmatrix.sync.aligned.m8n8.x4.shared.b16 {%0,%1,%2,%3}, [%4];"
        : "=r"(r[0]), "=r"(r[1]), "=r"(r[2]), "=r"(r[3]) : "r"(addr));
}
__device__ __forceinline__ void mma16816(float* d, const uint32_t* a, uint32_t b0, uint32_t b1) {
    asm volatile("mma.sync.aligned.m16n8k16.row.col.f32.f16.f16.f32 "
        "{%0,%1,%2,%3}, {%4,%5,%6,%7}, {%8,%9}, {%0,%1,%2,%3};"
        : "+f"(d[0]), "+f"(d[1]), "+f"(d[2]), "+f"(d[3])
        : "r"(a[0]), "r"(a[1]), "r"(a[2]), "r"(a[3]), "r"(b0), "r"(b1));
}

// ================= fused prep: softmax(->transposed) | transpose_W | convert_x | pad_b =================
#define PREP_TW   1024
#define PREP_CX   3072
#define PREP_PB   7168
#define PREP_GRID 7172

__global__ __launch_bounds__(256) void prep_fused(
    const float* __restrict__ x, const float* __restrict__ W,
    const float* __restrict__ b, const float* __restrict__ ld)
{
    __shared__ float smem_u[32 * 33];
    int bid = blockIdx.x;
    int tid = threadIdx.x;

    if (bid < PREP_TW) {
        // ---- softmax row of leaf_dist, written DIRECTLY transposed into g_lpTh[cls][leaf] ----
        int row = bid;     // leaf index
        const float* r = ld + (size_t)row * CN_;
        float* sred = smem_u;

        float mx = -3.4e38f;
        for (int i = tid; i < CN_; i += 256) mx = fmaxf(mx, r[i]);
        #pragma unroll
        for (int s = 16; s; s >>= 1) mx = fmaxf(mx, __shfl_xor_sync(0xffffffffu, mx, s));
        if ((tid & 31) == 0) sred[tid >> 5] = mx;
        __syncthreads();
        mx = sred[0];
        #pragma unroll
        for (int w = 1; w < 8; w++) mx = fmaxf(mx, sred[w]);
        __syncthreads();

        float sum = 0.0f;
        for (int i = tid; i < CN_; i += 256) sum += __expf(r[i] - mx);
        #pragma unroll
        for (int s = 16; s; s >>= 1) sum += __shfl_xor_sync(0xffffffffu, sum, s);
        if ((tid & 31) == 0) sred[tid >> 5] = sum;
        __syncthreads();
        sum = 0.0f;
        #pragma unroll
        for (int w = 0; w < 8; w++) sum += sred[w];
        float inv = 1.0f / sum;

        for (int i = tid; i < CN_; i += 256)
            g_lpTh[(size_t)i * NL_ + row] = __float2half_rn(__expf(r[i] - mx) * inv);
        for (int i = CN_ + tid; i < NL_; i += 256)
            g_lpTh[(size_t)i * NL_ + row] = __float2half_rn(0.0f);
    } else if (bid < PREP_CX) {
        // ---- W [2048 k][1023 n] -> g_WhT [1024 n][2048 k] fp16, pad with 0 ----
        int b2 = bid - PREP_TW;
        int k0 = (b2 & 63) * 32;
        int n0 = (b2 >> 6) * 32;
        int tx = tid & 31, ty = tid >> 5;
        float* t = smem_u;
        #pragma unroll
        for (int i = 0; i < 32; i += 8) {
            int n = n0 + tx;
            t[(ty + i) * 33 + tx] = (n < NI_) ? W[(size_t)(k0 + ty + i) * NI_ + n] : 0.0f;
        }
        __syncthreads();
        #pragma unroll
        for (int i = 0; i < 32; i += 8)
            g_WhT[(size_t)(n0 + ty + i) * DN_ + k0 + tx] = __float2half_rn(t[tx * 33 + ty + i]);
    } else if (bid < PREP_PB) {
        // ---- x fp32 -> fp16, 16 elems per thread ----
        int b2 = bid - PREP_CX;
        size_t i = ((size_t)b2 * 256 + tid) * 16;
        #pragma unroll
        for (int q = 0; q < 2; q++) {
            float4 v0 = *(const float4*)(x + i + q * 8);
            float4 v1 = *(const float4*)(x + i + q * 8 + 4);
            __half2 h[4];
            h[0] = __floats2half2_rn(v0.x, v0.y);
            h[1] = __floats2half2_rn(v0.z, v0.w);
            h[2] = __floats2half2_rn(v1.x, v1.y);
            h[3] = __floats2half2_rn(v1.z, v1.w);
            *(uint4*)(g_xh + i + q * 8) = *(uint4*)h;
        }
    } else {
        int i = (bid - PREP_PB) * 256 + tid;
        if (i < NL_) g_bp[i] = (i < NI_) ? b[i] : 0.0f;
    }
}

// ================= pp unwind (verified, sync-free) =================
__global__ __launch_bounds__(256) void pp_kernel() {
    __shared__ float ds[NL_];
    int row = blockIdx.x;
    int tid = threadIdx.x;
    const float* dr = g_dec + (size_t)row * NL_;
    for (int i = tid; i < NL_; i += 256) ds[i] = dr[i];
    __syncthreads();

    __half* po = g_pph + (size_t)row * NL_;
    #pragma unroll
    for (int jj = 0; jj < 4; jj++) {
        int j = tid + jj * 256;
        float p = 1.0f;
        int idx = j;
        #pragma unroll
        for (int d = 9; d >= 0; d--) {
            int L = 1 << d;
            int i2 = (idx < L) ? (idx << 1) : (((idx - L) << 1) | 1);
            bool left = i2 < L;
            int node = (L - 1) + (left ? i2 : (i2 - L));
            float dd = ds[node];
            p *= left ? dd : (1.0f - dd);
            idx = i2 & (L - 1);
        }
        po[j] = __float2half_rn(p);
    }
}

// ---------------- fp16 mma.sync GEMM: 128x128x64, 256 threads (8 warps x 32x64), 3-stage ----------------
#define BM   128
#define BNT  128
#define BKH  64                                   // k-tile in halves
#define STG  3
#define PADH 72                                   // halves per smem row (144B)
#define SSTAGE_H ((BM + BNT) * PADH)              // halves per stage = 18432
#define SMEM_GEMM (STG * SSTAGE_H * 2)            // 110592 bytes

template <bool SIG>
__global__ __launch_bounds__(256, 2) void gemm_h(
    const __half* __restrict__ A, const __half* __restrict__ Bm,
    const float* __restrict__ bias, float* __restrict__ C,
    int K, int lda, int ldb, int ldc, int nvalid)
{
    extern __shared__ __half smh[];
    const int tid  = threadIdx.x;
    const int wid  = tid >> 5, lane = tid & 31;
    const int gid  = lane >> 2, tig = lane & 3;
    const int m0   = (wid & 3) * 32, n0 = (wid >> 2) * 64;   // warp tile 32x64
    const int rowBase = blockIdx.y * BM;
    const int colBase = blockIdx.x * BNT;
    const uint32_t sb = smem_u32(smh);

    const __half* Ag = A + (size_t)rowBase * lda;
    const __half* Bg = Bm + (size_t)colBase * ldb;

    // ldmatrix lane addressing (R5-verified mapping)
    const int lrow  = (lane & 7) + ((lane >> 3) & 1) * 8;
    const int khalf = (lane >> 4) * 8;
    uint32_t offA[2], offB[4];
    #pragma unroll
    for (int mf = 0; mf < 2; mf++)
        offA[mf] = (uint32_t)(((m0 + mf * 16 + lrow) * PADH + khalf) * 2);
    #pragma unroll
    for (int p = 0; p < 4; p++)
        offB[p] = (uint32_t)((BM * PADH + (n0 + p * 16 + lrow) * PADH + khalf) * 2);

    float acc[2][8][4];
    #pragma unroll
    for (int mf = 0; mf < 2; mf++)
        #pragma unroll
        for (int nf = 0; nf < 8; nf++)
            #pragma unroll
            for (int q = 0; q < 4; q++) acc[mf][nf][q] = 0.0f;

    const int nkt = K / BKH;

    // stage loader: 256 rows x 128B = 2048 x 16B chunks, 8 per thread
    auto load_stage = [&](int s, int kt) {
        uint32_t abase = sb + (uint32_t)(s * SSTAGE_H) * 2;
        uint32_t bbase = abase + BM * PADH * 2;
        const __half* Ak = Ag + kt * BKH;
        const __half* Bk = Bg + kt * BKH;
        #pragma unroll
        for (int i = 0; i < 4; i++) {
            int idx = tid + i * 256;
            int row = idx >> 3, ch = idx & 7;
            cpasync16(abase + (uint32_t)(row * PADH * 2 + ch * 16), Ak + (size_t)row * lda + ch * 8);
        }
        #pragma unroll
        for (int i = 0; i < 4; i++) {
            int idx = tid + i * 256;
            int row = idx >> 3, ch = idx & 7;
            cpasync16(bbase + (uint32_t)(row * PADH * 2 + ch * 16), Bk + (size_t)row * ldb + ch * 8);
        }
    };

    load_stage(0, 0);
    asm volatile("cp.async.commit_group;" ::: "memory");
    load_stage(1, 1);
    asm volatile("cp.async.commit_group;" ::: "memory");

    int stage = 0;
    for (int kt = 0; kt < nkt; kt++) {
        asm volatile("cp.async.wait_group 1;" ::: "memory");
        __syncthreads();

        if (kt + 2 < nkt) {
            int s2 = stage + 2; if (s2 >= STG) s2 -= STG;
            load_stage(s2, kt + 2);
        }
        asm volatile("cp.async.commit_group;" ::: "memory");

        uint32_t sbase = sb + (uint32_t)(stage * SSTAGE_H) * 2;
        #pragma unroll
        for (int ks = 0; ks < 4; ks++) {
            const uint32_t kb = ks * 32;   // 16 halves per kstep
            uint32_t a[2][4], b[4][4];
            #pragma unroll
            for (int mf = 0; mf < 2; mf++) ldsm4(a[mf], sbase + offA[mf] + kb);
            #pragma unroll
            for (int p = 0; p < 4; p++)   ldsm4(b[p],  sbase + offB[p] + kb);
            // b[p]: r0=(nlo,klo) r1=(nhi,klo) r2=(nlo,khi) r3=(nhi,khi)
            #pragma unroll
            for (int mf = 0; mf < 2; mf++)
                #pragma unroll
                for (int p = 0; p < 4; p++) {
                    mma16816(acc[mf][2 * p],     a[mf], b[p][0], b[p][2]);
                    mma16816(acc[mf][2 * p + 1], a[mf], b[p][1], b[p][3]);
                }
        }
        stage++; if (stage == STG) stage = 0;
    }

    // epilogue
    #pragma unroll
    for (int mf = 0; mf < 2; mf++) {
        int r0 = rowBase + m0 + mf * 16 + gid;
        #pragma unroll
        for (int nf = 0; nf < 8; nf++) {
            int col = colBase + n0 + nf * 8 + tig * 2;
            float2 v0 = make_float2(acc[mf][nf][0], acc[mf][nf][1]);
            float2 v1 = make_float2(acc[mf][nf][2], acc[mf][nf][3]);
            if (SIG) {
                float b0 = bias[col], b1 = bias[col + 1];
                v0.x = 1.0f / (1.0f + __expf(-(v0.x + b0)));
                v0.y = 1.0f / (1.0f + __expf(-(v0.y + b1)));
                v1.x = 1.0f / (1.0f + __expf(-(v1.x + b0)));
                v1.y = 1.0f / (1.0f + __expf(-(v1.y + b1)));
            }
            if (col < nvalid) {
                *(float2*)(C + (size_t)r0 * ldc + col) = v0;
                *(float2*)(C + (size_t)(r0 + 8) * ldc + col) = v1;
            }
        }
    }
}

// ---------------- host launch ----------------
extern "C" void kernel_launch(void* const* d_in, const int* in_sizes, int n_in,
                              void* d_out, int out_size)
{
    const float* x    = (const float*)d_in[0];   // [8192, 2048]
    const float* W    = (const float*)d_in[1];   // [2048, 1023]
    const float* b    = (const float*)d_in[2];   // [1023]
    const float* leaf = (const float*)d_in[3];   // [1024, 1000]
    float*       out  = (float*)d_out;           // [8192, 1000]

    __half *xh, *WhT, *pph, *lpTh;
    float *bp, *dec;
    cudaGetSymbolAddress((void**)&xh,   g_xh);
    cudaGetSymbolAddress((void**)&WhT,  g_WhT);
    cudaGetSymbolAddress((void**)&bp,   g_bp);
    cudaGetSymbolAddress((void**)&dec,  g_dec);
    cudaGetSymbolAddress((void**)&pph,  g_pph);
    cudaGetSymbolAddress((void**)&lpTh, g_lpTh);

    static bool attr_set = false;
    if (!attr_set) {
        cudaFuncSetAttribute(gemm_h<true>,  cudaFuncAttributeMaxDynamicSharedMemorySize, SMEM_GEMM);
        cudaFuncSetAttribute(gemm_h<false>, cudaFuncAttributeMaxDynamicSharedMemorySize, SMEM_GEMM);
        attr_set = true;
    }

    // 1) fused prep: softmax (direct transposed write) | transpose_W | convert_x | pad_b
    prep_fused<<<PREP_GRID, 256>>>(x, W, b, leaf);

    // 2) decisions = sigmoid(x @ W + b)   [8192,1024] fp32
    gemm_h<true><<<dim3(NL_ / BNT, BN_ / BM), 256, SMEM_GEMM>>>(
        xh, WhT, bp, dec, DN_, DN_, DN_, NL_, NL_);

    // 3) pp unwind -> fp16 [8192,1024]
    pp_kernel<<<BN_, 256>>>();

    // 4) out = pp @ leaf_probs   [8192,1000]
    gemm_h<false><<<dim3(NL_ / BNT, BN_ / BM), 256, SMEM_GEMM>>>(
        pph, lpTh, nullptr, out, NL_, NL_, NL_, CN_, CN_);
}

// round 17
// speedup vs baseline: 1.2113x; 1.0590x over previous
#include <cuda_runtime.h>
#include <cuda_fp16.h>
#include <stdint.h>
#include <math.h>

// ---------------- problem constants ----------------
#define BN_ 8192   // batch
#define DN_ 2048   // feature dim
#define NI_ 1023   // inner nodes
#define NL_ 1024   // leaves / padded inner count
#define CN_ 1000   // classes

// ---------------- device-global scratch ----------------
__device__ __half g_xh[(size_t)BN_ * DN_];        // x in fp16
__device__ __half g_WhT[NL_ * DN_];               // W^T padded fp16: [1024 n][2048 k]
__device__ float  g_bp[NL_];
__device__ __half g_dech[(size_t)BN_ * NL_];      // decisions fp16 [8192][1024]
__device__ __half g_pph[(size_t)BN_ * NL_];       // path probs fp16 [8192][1024]
__device__ float  g_lp[NL_ * NL_];                // softmax(leaf) fp32 [1024][1024]
__device__ __half g_lpTh[NL_ * NL_];              // transposed fp16 [1024 cls][1024 leaf]

// ---------------- helpers ----------------
__device__ __forceinline__ uint32_t smem_u32(const void* p) {
    uint32_t a;
    asm("{ .reg .u64 t; cvta.to.shared.u64 t, %1; cvt.u32.u64 %0, t; }" : "=r"(a) : "l"(p));
    return a;
}
__device__ __forceinline__ void cpasync16(uint32_t dst, const void* src) {
    asm volatile("cp.async.cg.shared.global [%0], [%1], 16;" :: "r"(dst), "l"(src) : "memory");
}
__device__ __forceinline__ void ldsm4(uint32_t* r, uint32_t addr) {
    asm volatile("ldmatrix.sync.aligned.m8n8.x4.shared.b16 {%0,%1,%2,%3}, [%4];"
        : "=r"(r[0]), "=r"(r[1]), "=r"(r[2]), "=r"(r[3]) : "r"(addr));
}
__device__ __forceinline__ void mma16816(float* d, const uint32_t* a, uint32_t b0, uint32_t b1) {
    asm volatile("mma.sync.aligned.m16n8k16.row.col.f32.f16.f16.f32 "
        "{%0,%1,%2,%3}, {%4,%5,%6,%7}, {%8,%9}, {%0,%1,%2,%3};"
        : "+f"(d[0]), "+f"(d[1]), "+f"(d[2]), "+f"(d[3])
        : "r"(a[0]), "r"(a[1]), "r"(a[2]), "r"(a[3]), "r"(b0), "r"(b1));
}

// ================= fused prep: softmax | transpose_W | convert_x | pad_b (R14-verified) =================
#define PREP_TW   1024
#define PREP_CX   3072
#define PREP_PB   7168
#define PREP_GRID 7172

__global__ __launch_bounds__(256) void prep_fused(
    const float* __restrict__ x, const float* __restrict__ W,
    const float* __restrict__ b, const float* __restrict__ ld)
{
    __shared__ float smem_u[32 * 33];
    int bid = blockIdx.x;
    int tid = threadIdx.x;

    if (bid < PREP_TW) {
        // ---- softmax row of leaf_dist -> g_lp [1024,1024] fp32, pad zeroed ----
        int row = bid;
        const float* r = ld + (size_t)row * CN_;
        float*       o = g_lp + (size_t)row * NL_;
        float* sred = smem_u;

        float mx = -3.4e38f;
        for (int i = tid; i < CN_; i += 256) mx = fmaxf(mx, r[i]);
        #pragma unroll
        for (int s = 16; s; s >>= 1) mx = fmaxf(mx, __shfl_xor_sync(0xffffffffu, mx, s));
        if ((tid & 31) == 0) sred[tid >> 5] = mx;
        __syncthreads();
        mx = sred[0];
        #pragma unroll
        for (int w = 1; w < 8; w++) mx = fmaxf(mx, sred[w]);
        __syncthreads();

        float sum = 0.0f;
        for (int i = tid; i < CN_; i += 256) sum += __expf(r[i] - mx);
        #pragma unroll
        for (int s = 16; s; s >>= 1) sum += __shfl_xor_sync(0xffffffffu, sum, s);
        if ((tid & 31) == 0) sred[tid >> 5] = sum;
        __syncthreads();
        sum = 0.0f;
        #pragma unroll
        for (int w = 0; w < 8; w++) sum += sred[w];
        float inv = 1.0f / sum;

        for (int i = tid; i < CN_; i += 256) o[i] = __expf(r[i] - mx) * inv;
        for (int i = CN_ + tid; i < NL_; i += 256) o[i] = 0.0f;
    } else if (bid < PREP_CX) {
        // ---- W [2048 k][1023 n] -> g_WhT [1024 n][2048 k] fp16, pad with 0 ----
        int b2 = bid - PREP_TW;
        int k0 = (b2 & 63) * 32;
        int n0 = (b2 >> 6) * 32;
        int tx = tid & 31, ty = tid >> 5;
        float* t = smem_u;
        #pragma unroll
        for (int i = 0; i < 32; i += 8) {
            int n = n0 + tx;
            t[(ty + i) * 33 + tx] = (n < NI_) ? W[(size_t)(k0 + ty + i) * NI_ + n] : 0.0f;
        }
        __syncthreads();
        #pragma unroll
        for (int i = 0; i < 32; i += 8)
            g_WhT[(size_t)(n0 + ty + i) * DN_ + k0 + tx] = __float2half_rn(t[tx * 33 + ty + i]);
    } else if (bid < PREP_PB) {
        // ---- x fp32 -> fp16, 16 elems per thread ----
        int b2 = bid - PREP_CX;
        size_t i = ((size_t)b2 * 256 + tid) * 16;
        #pragma unroll
        for (int q = 0; q < 2; q++) {
            float4 v0 = *(const float4*)(x + i + q * 8);
            float4 v1 = *(const float4*)(x + i + q * 8 + 4);
            __half2 h[4];
            h[0] = __floats2half2_rn(v0.x, v0.y);
            h[1] = __floats2half2_rn(v0.z, v0.w);
            h[2] = __floats2half2_rn(v1.x, v1.y);
            h[3] = __floats2half2_rn(v1.z, v1.w);
            *(uint4*)(g_xh + i + q * 8) = *(uint4*)h;
        }
    } else {
        int i = (bid - PREP_PB) * 256 + tid;
        if (i < NL_) g_bp[i] = (i < NI_) ? b[i] : 0.0f;
    }
}

// ================= fused mid: pp unwind (fp16 dec) | transpose_lp =================
#define MID_TL  8192
#define MID_GRID 9216

__global__ __launch_bounds__(256) void mid_fused() {
    __shared__ float smem_u[32 * 33 > NL_ ? 32 * 33 : NL_];
    int bid = blockIdx.x;
    int tid = threadIdx.x;

    if (bid < MID_TL) {
        // ---- pp unwind, dec read as fp16 ----
        int row = bid;
        float* ds = smem_u;
        const __half* dr = g_dech + (size_t)row * NL_;
        for (int i = tid; i < NL_; i += 256) ds[i] = __half2float(dr[i]);
        __syncthreads();

        __half* po = g_pph + (size_t)row * NL_;
        #pragma unroll
        for (int jj = 0; jj < 4; jj++) {
            int j = tid + jj * 256;
            float p = 1.0f;
            int idx = j;
            #pragma unroll
            for (int d = 9; d >= 0; d--) {
                int L = 1 << d;
                int i2 = (idx < L) ? (idx << 1) : (((idx - L) << 1) | 1);
                bool left = i2 < L;
                int node = (L - 1) + (left ? i2 : (i2 - L));
                float dd = ds[node];
                p *= left ? dd : (1.0f - dd);
                idx = i2 & (L - 1);
            }
            po[j] = __float2half_rn(p);
        }
    } else {
        // ---- g_lp [leaf][cls] fp32 -> g_lpTh [cls][leaf] fp16 ----
        int b2 = bid - MID_TL;
        int r0 = (b2 & 31) * 32, c0 = (b2 >> 5) * 32;
        int tx = tid & 31, ty = tid >> 5;
        float* t = smem_u;
        #pragma unroll
        for (int i = 0; i < 32; i += 8)
            t[(ty + i) * 33 + tx] = g_lp[(size_t)(r0 + ty + i) * NL_ + c0 + tx];
        __syncthreads();
        #pragma unroll
        for (int i = 0; i < 32; i += 8)
            g_lpTh[(size_t)(c0 + ty + i) * NL_ + r0 + tx] = __float2half_rn(t[tx * 33 + ty + i]);
    }
}

// ---------------- fp16 mma.sync GEMM: 128x128x64, 256 threads (8 warps x 32x64), 3-stage ----------------
// SIG=true: apply bias+sigmoid, write __half output; SIG=false: write float output.
#define BM   128
#define BNT  128
#define BKH  64                                   // k-tile in halves
#define STG  3
#define PADH 72                                   // halves per smem row (144B)
#define SSTAGE_H ((BM + BNT) * PADH)              // halves per stage = 18432
#define SMEM_GEMM (STG * SSTAGE_H * 2)            // 110592 bytes

template <bool SIG>
__global__ __launch_bounds__(256, 2) void gemm_h(
    const __half* __restrict__ A, const __half* __restrict__ Bm,
    const float* __restrict__ bias, void* __restrict__ Cv,
    int K, int lda, int ldb, int ldc, int nvalid)
{
    extern __shared__ __half smh[];
    const int tid  = threadIdx.x;
    const int wid  = tid >> 5, lane = tid & 31;
    const int gid  = lane >> 2, tig = lane & 3;
    const int m0   = (wid & 3) * 32, n0 = (wid >> 2) * 64;   // warp tile 32x64
    const int rowBase = blockIdx.y * BM;
    const int colBase = blockIdx.x * BNT;
    const uint32_t sb = smem_u32(smh);

    const __half* Ag = A + (size_t)rowBase * lda;
    const __half* Bg = Bm + (size_t)colBase * ldb;

    // ldmatrix lane addressing (R5-verified mapping)
    const int lrow  = (lane & 7) + ((lane >> 3) & 1) * 8;
    const int khalf = (lane >> 4) * 8;
    uint32_t offA[2], offB[4];
    #pragma unroll
    for (int mf = 0; mf < 2; mf++)
        offA[mf] = (uint32_t)(((m0 + mf * 16 + lrow) * PADH + khalf) * 2);
    #pragma unroll
    for (int p = 0; p < 4; p++)
        offB[p] = (uint32_t)((BM * PADH + (n0 + p * 16 + lrow) * PADH + khalf) * 2);

    float acc[2][8][4];
    #pragma unroll
    for (int mf = 0; mf < 2; mf++)
        #pragma unroll
        for (int nf = 0; nf < 8; nf++)
            #pragma unroll
            for (int q = 0; q < 4; q++) acc[mf][nf][q] = 0.0f;

    const int nkt = K / BKH;

    // stage loader: 256 rows x 128B = 2048 x 16B chunks, 8 per thread
    auto load_stage = [&](int s, int kt) {
        uint32_t abase = sb + (uint32_t)(s * SSTAGE_H) * 2;
        uint32_t bbase = abase + BM * PADH * 2;
        const __half* Ak = Ag + kt * BKH;
        const __half* Bk = Bg + kt * BKH;
        #pragma unroll
        for (int i = 0; i < 4; i++) {
            int idx = tid + i * 256;
            int row = idx >> 3, ch = idx & 7;
            cpasync16(abase + (uint32_t)(row * PADH * 2 + ch * 16), Ak + (size_t)row * lda + ch * 8);
        }
        #pragma unroll
        for (int i = 0; i < 4; i++) {
            int idx = tid + i * 256;
            int row = idx >> 3, ch = idx & 7;
            cpasync16(bbase + (uint32_t)(row * PADH * 2 + ch * 16), Bk + (size_t)row * ldb + ch * 8);
        }
    };

    load_stage(0, 0);
    asm volatile("cp.async.commit_group;" ::: "memory");
    load_stage(1, 1);
    asm volatile("cp.async.commit_group;" ::: "memory");

    int stage = 0;
    for (int kt = 0; kt < nkt; kt++) {
        asm volatile("cp.async.wait_group 1;" ::: "memory");
        __syncthreads();

        if (kt + 2 < nkt) {
            int s2 = stage + 2; if (s2 >= STG) s2 -= STG;
            load_stage(s2, kt + 2);
        }
        asm volatile("cp.async.commit_group;" ::: "memory");

        uint32_t sbase = sb + (uint32_t)(stage * SSTAGE_H) * 2;
        #pragma unroll
        for (int ks = 0; ks < 4; ks++) {
            const uint32_t kb = ks * 32;   // 16 halves per kstep
            uint32_t a[2][4], b[4][4];
            #pragma unroll
            for (int mf = 0; mf < 2; mf++) ldsm4(a[mf], sbase + offA[mf] + kb);
            #pragma unroll
            for (int p = 0; p < 4; p++)   ldsm4(b[p],  sbase + offB[p] + kb);
            // b[p]: r0=(nlo,klo) r1=(nhi,klo) r2=(nlo,khi) r3=(nhi,khi)
            #pragma unroll
            for (int mf = 0; mf < 2; mf++)
                #pragma unroll
                for (int p = 0; p < 4; p++) {
                    mma16816(acc[mf][2 * p],     a[mf], b[p][0], b[p][2]);
                    mma16816(acc[mf][2 * p + 1], a[mf], b[p][1], b[p][3]);
                }
        }
        stage++; if (stage == STG) stage = 0;
    }

    // epilogue
    #pragma unroll
    for (int mf = 0; mf < 2; mf++) {
        int r0 = rowBase + m0 + mf * 16 + gid;
        #pragma unroll
        for (int nf = 0; nf < 8; nf++) {
            int col = colBase + n0 + nf * 8 + tig * 2;
            float2 v0 = make_float2(acc[mf][nf][0], acc[mf][nf][1]);
            float2 v1 = make_float2(acc[mf][nf][2], acc[mf][nf][3]);
            if (SIG) {
                float b0 = bias[col], b1 = bias[col + 1];
                v0.x = 1.0f / (1.0f + __expf(-(v0.x + b0)));
                v0.y = 1.0f / (1.0f + __expf(-(v0.y + b1)));
                v1.x = 1.0f / (1.0f + __expf(-(v1.x + b0)));
                v1.y = 1.0f / (1.0f + __expf(-(v1.y + b1)));
                // fp16 output (decisions)
                __half* C = (__half*)Cv;
                *(__half2*)(C + (size_t)r0 * ldc + col)       = __floats2half2_rn(v0.x, v0.y);
                *(__half2*)(C + (size_t)(r0 + 8) * ldc + col) = __floats2half2_rn(v1.x, v1.y);
            } else {
                float* C = (float*)Cv;
                if (col < nvalid) {
                    *(float2*)(C + (size_t)r0 * ldc + col) = v0;
                    *(float2*)(C + (size_t)(r0 + 8) * ldc + col) = v1;
                }
            }
        }
    }
}

// ---------------- host launch ----------------
extern "C" void kernel_launch(void* const* d_in, const int* in_sizes, int n_in,
                              void* d_out, int out_size)
{
    const float* x    = (const float*)d_in[0];   // [8192, 2048]
    const float* W    = (const float*)d_in[1];   // [2048, 1023]
    const float* b    = (const float*)d_in[2];   // [1023]
    const float* leaf = (const float*)d_in[3];   // [1024, 1000]
    float*       out  = (float*)d_out;           // [8192, 1000]

    __half *xh, *WhT, *dech, *pph, *lpTh;
    float *bp;
    cudaGetSymbolAddress((void**)&xh,   g_xh);
    cudaGetSymbolAddress((void**)&WhT,  g_WhT);
    cudaGetSymbolAddress((void**)&bp,   g_bp);
    cudaGetSymbolAddress((void**)&dech, g_dech);
    cudaGetSymbolAddress((void**)&pph,  g_pph);
    cudaGetSymbolAddress((void**)&lpTh, g_lpTh);

    static bool attr_set = false;
    if (!attr_set) {
        cudaFuncSetAttribute(gemm_h<true>,  cudaFuncAttributeMaxDynamicSharedMemorySize, SMEM_GEMM);
        cudaFuncSetAttribute(gemm_h<false>, cudaFuncAttributeMaxDynamicSharedMemorySize, SMEM_GEMM);
        attr_set = true;
    }

    // 1) fused prep: softmax | transpose_W | convert_x | pad_b
    prep_fused<<<PREP_GRID, 256>>>(x, W, b, leaf);

    // 2) decisions = sigmoid(x @ W + b)   [8192,1024] fp16
    gemm_h<true><<<dim3(NL_ / BNT, BN_ / BM), 256, SMEM_GEMM>>>(
        xh, WhT, bp, dech, DN_, DN_, DN_, NL_, NL_);

    // 3) fused mid: pp unwind (fp16 dec) | transpose_lp
    mid_fused<<<MID_GRID, 256>>>();

    // 4) out = pp @ leaf_probs   [8192,1000] fp32
    gemm_h<false><<<dim3(NL_ / BNT, BN_ / BM), 256, SMEM_GEMM>>>(
        pph, lpTh, nullptr, out, NL_, NL_, NL_, CN_, CN_);
}